// round 3
// baseline (speedup 1.0000x reference)
#include <cuda_runtime.h>
#include <cuda_bf16.h>
#include <cstdint>

#define NB 16384
#define NF 256
#define NH 256
#define NC 10
#define NT 100
#define BF (NB * NF)

#define DT_TAU_MEM 0.1f
#define SYN_DECAY  0.8f

// ---- device scratch (static, no allocation) ----
__device__ unsigned short g_Z[(size_t)NT * BF];     // layer-1 spikes, bf16 {0,1}
__device__ unsigned short g_Ws[3][NH * NF];         // W_hidden 3-way bf16 split
__device__ float          g_ms[(size_t)NB * NH];    // mean spike counts

// ================= kernel 0: split W into 3 bf16 planes =================
__global__ void k_split(const float* __restrict__ W) {
    int i = blockIdx.x * blockDim.x + threadIdx.x;
    if (i >= NH * NF) return;
    float w = W[i];
    __nv_bfloat16 hi = __float2bfloat16(w);
    float r1 = w - __bfloat162float(hi);
    __nv_bfloat16 mid = __float2bfloat16(r1);
    float r2 = r1 - __bfloat162float(mid);
    __nv_bfloat16 lo = __float2bfloat16(r2);
    g_Ws[0][i] = *(unsigned short*)&hi;
    g_Ws[1][i] = *(unsigned short*)&mid;
    g_Ws[2][i] = *(unsigned short*)&lo;
}

// ================= kernel 1: layer-1 LIF spike trains =================
__global__ void k_spike(const float* __restrict__ X) {
    int gid = (blockIdx.x * blockDim.x + threadIdx.x) * 4;
    float x0 = X[gid], x1 = X[gid + 1], x2 = X[gid + 2], x3 = X[gid + 3];
    float v0 = 0.f, v1 = 0.f, v2 = 0.f, v3 = 0.f;
    float c0 = 0.f, c1 = 0.f, c2 = 0.f, c3 = 0.f;
    const unsigned short ONE = 0x3F80u, ZER = 0u;
    for (int t = 0; t < NT; ++t) {
        float d0 = fmaf(DT_TAU_MEM, c0 - v0, v0);
        float d1 = fmaf(DT_TAU_MEM, c1 - v1, v1);
        float d2 = fmaf(DT_TAU_MEM, c2 - v2, v2);
        float d3 = fmaf(DT_TAU_MEM, c3 - v3, v3);
        bool z0 = d0 > 1.0f, z1 = d1 > 1.0f, z2 = d2 > 1.0f, z3 = d3 > 1.0f;
        ushort4 pk = make_ushort4(z0 ? ONE : ZER, z1 ? ONE : ZER,
                                  z2 ? ONE : ZER, z3 ? ONE : ZER);
        reinterpret_cast<ushort4*>(g_Z + (size_t)t * BF)[gid >> 2] = pk;
        v0 = z0 ? 0.f : d0; v1 = z1 ? 0.f : d1;
        v2 = z2 ? 0.f : d2; v3 = z3 ? 0.f : d3;
        c0 = __fadd_rn(__fmul_rn(c0, SYN_DECAY), x0);
        c1 = __fadd_rn(__fmul_rn(c1, SYN_DECAY), x1);
        c2 = __fadd_rn(__fmul_rn(c2, SYN_DECAY), x2);
        c3 = __fadd_rn(__fmul_rn(c3, SYN_DECAY), x3);
    }
}

// ================= kernel 2: fused GEMM + layer-2 LIF scan =================
// CTA: 64 b-rows x 64 h-cols, 128 thr (2x2 warps, 32x32 warp tiles).
// W (3 splits) SMEM-resident; Z tile double-buffered via cp.async.

#define SROW_B 528                          // padded row bytes (264 bf16)
#define ROWSTEP16 8448                      // 16 * SROW_B
#define SW_BYTES (3 * 64 * SROW_B)          // 101376
#define SA_BYTES (64 * SROW_B)              // 33792
#define SMEM_TOTAL (SW_BYTES + 2 * SA_BYTES)

#define LDSM4(R, ADDR) asm volatile( \
    "ldmatrix.sync.aligned.m8n8.x4.shared.b16 {%0,%1,%2,%3}, [%4];" \
    : "=r"((R)[0]), "=r"((R)[1]), "=r"((R)[2]), "=r"((R)[3]) : "r"(ADDR))

#define MMA(D, A, B0, B1) asm volatile( \
    "mma.sync.aligned.m16n8k16.row.col.f32.bf16.bf16.f32 " \
    "{%0,%1,%2,%3},{%4,%5,%6,%7},{%8,%9},{%0,%1,%2,%3};" \
    : "+f"((D)[0]), "+f"((D)[1]), "+f"((D)[2]), "+f"((D)[3]) \
    : "r"((A)[0]), "r"((A)[1]), "r"((A)[2]), "r"((A)[3]), "r"(B0), "r"(B1))

__device__ __forceinline__ void cp16(uint32_t dst, const void* src) {
    asm volatile("cp.async.cg.shared.global [%0], [%1], 16;" :: "r"(dst), "l"(src));
}
__device__ __forceinline__ void cp_commit() { asm volatile("cp.async.commit_group;"); }
__device__ __forceinline__ void cp_wait0()  { asm volatile("cp.async.wait_group 0;"); }

__global__ void __launch_bounds__(128, 1)
k_fused(const float* __restrict__ bhid) {
    extern __shared__ char smem[];
    const uint32_t su = (uint32_t)__cvta_generic_to_shared(smem);
    const uint32_t wbase = su;
    const uint32_t zbase0 = su + SW_BYTES;
    const uint32_t zbase1 = su + SW_BYTES + SA_BYTES;

    const int tid = threadIdx.x;
    const int warp = tid >> 5, lane = tid & 31;
    const int warp_m = warp >> 1, warp_n = warp & 1;
    const int hTile = blockIdx.x, bTile = blockIdx.y;

    // ---- prologue: load W tiles (3 splits) + Z(t=0) via cp.async ----
    {
        // W: 3 * 64 rows * 512B = 6144 16B-chunks
        for (int i = 0; i < 48; ++i) {
            int idx = tid + i * 128;
            int s = idx >> 11, rem = idx & 2047;
            int row = rem >> 5, ch = rem & 31;
            const char* src = (const char*)g_Ws[s] + ((size_t)(hTile * 64 + row) * 512) + ch * 16;
            cp16(wbase + s * SA_BYTES + row * SROW_B + ch * 16, src);
        }
        // Z(0): 64 rows * 512B = 2048 chunks
        const char* zsrc = (const char*)(g_Z) + (size_t)(bTile * 64) * 512;
        for (int i = 0; i < 16; ++i) {
            int idx = tid + i * 128;
            int row = idx >> 5, ch = idx & 31;
            cp16(zbase0 + row * SROW_B + ch * 16, zsrc + (size_t)row * 512 + ch * 16);
        }
        cp_commit();
        cp_wait0();
        __syncthreads();
    }

    // bias values for this thread's 8 h columns
    const int c2 = (lane & 3) * 2;
    const int r4 = lane >> 2;
    float bhv[8];
    #pragma unroll
    for (int nt = 0; nt < 4; ++nt)
        #pragma unroll
        for (int e1 = 0; e1 < 2; ++e1)
            bhv[nt * 2 + e1] = bhid[hTile * 64 + warp_n * 32 + nt * 8 + c2 + e1];

    // per-lane ldmatrix row offsets
    const uint32_t aOff = (uint32_t)((warp_m * 32 + (lane & 15)) * SROW_B + (lane >> 4) * 16);
    const uint32_t bOff = (uint32_t)((warp_n * 32 + (lane & 15)) * SROW_B + (lane >> 4) * 16);

    float v2[32], i2[32], cnt[32];
    #pragma unroll
    for (int i = 0; i < 32; ++i) { v2[i] = 0.f; i2[i] = 0.f; cnt[i] = 0.f; }

    for (int t = 0; t < NT; ++t) {
        // prefetch Z(t+1) into other buffer
        if (t < NT - 1) {
            uint32_t dst = ((t + 1) & 1) ? zbase1 : zbase0;
            const char* zsrc = (const char*)g_Z + (size_t)(t + 1) * BF * 2 + (size_t)(bTile * 64) * 512;
            for (int i = 0; i < 16; ++i) {
                int idx = tid + i * 128;
                int row = idx >> 5, ch = idx & 31;
                cp16(dst + row * SROW_B + ch * 16, zsrc + (size_t)row * 512 + ch * 16);
            }
            cp_commit();
        }

        const uint32_t zb = (t & 1) ? zbase1 : zbase0;
        float acc[2][4][4];
        #pragma unroll
        for (int mt = 0; mt < 2; ++mt)
            #pragma unroll
            for (int nt = 0; nt < 4; ++nt)
                #pragma unroll
                for (int e = 0; e < 4; ++e) acc[mt][nt][e] = 0.f;

        #pragma unroll 4
        for (int kc = 0; kc < 16; ++kc) {
            uint32_t a[2][4];
            LDSM4(a[0], zb + aOff + kc * 32);
            LDSM4(a[1], zb + aOff + ROWSTEP16 + kc * 32);
            #pragma unroll
            for (int s = 0; s < 3; ++s) {
                uint32_t b0[4], b1[4];
                LDSM4(b0, wbase + s * SA_BYTES + bOff + kc * 32);
                LDSM4(b1, wbase + s * SA_BYTES + bOff + ROWSTEP16 + kc * 32);
                #pragma unroll
                for (int mt = 0; mt < 2; ++mt) {
                    MMA(acc[mt][0], a[mt], b0[0], b0[2]);
                    MMA(acc[mt][1], a[mt], b0[1], b0[3]);
                    MMA(acc[mt][2], a[mt], b1[0], b1[2]);
                    MMA(acc[mt][3], a[mt], b1[1], b1[3]);
                }
            }
        }

        // fused layer-2 LIF update
        #pragma unroll
        for (int mt = 0; mt < 2; ++mt)
            #pragma unroll
            for (int nt = 0; nt < 4; ++nt)
                #pragma unroll
                for (int e = 0; e < 4; ++e) {
                    int s = (mt * 4 + nt) * 4 + e;
                    float h = acc[mt][nt][e] + bhv[nt * 2 + (e & 1)];
                    float vd = fmaf(DT_TAU_MEM, i2[s] - v2[s], v2[s]);
                    bool z = vd > 1.0f;
                    cnt[s] += z ? 1.0f : 0.0f;
                    v2[s] = z ? 0.0f : vd;
                    i2[s] = __fadd_rn(__fmul_rn(i2[s], SYN_DECAY), h);
                }

        if (t < NT - 1) { cp_wait0(); __syncthreads(); }
    }

    // write mean spikes
    #pragma unroll
    for (int mt = 0; mt < 2; ++mt)
        #pragma unroll
        for (int nt = 0; nt < 4; ++nt)
            #pragma unroll
            for (int e = 0; e < 4; ++e) {
                int s = (mt * 4 + nt) * 4 + e;
                int gb = bTile * 64 + warp_m * 32 + mt * 16 + r4 + (e >> 1) * 8;
                int gh = hTile * 64 + warp_n * 32 + nt * 8 + c2 + (e & 1);
                g_ms[(size_t)gb * NH + gh] = cnt[s] / 100.0f;
            }
}

// ================= kernel 3: readout =================
__global__ void k_readout(const float* __restrict__ Wr,
                          const float* __restrict__ br,
                          float* __restrict__ out) {
    int warp = threadIdx.x >> 5, lane = threadIdx.x & 31;
    int b = blockIdx.x * 8 + warp;
    const float4* msp = reinterpret_cast<const float4*>(g_ms + (size_t)b * NH);
    float4 m0 = msp[lane * 2], m1 = msp[lane * 2 + 1];
    float mv[8] = {m0.x, m0.y, m0.z, m0.w, m1.x, m1.y, m1.z, m1.w};
    float p[NC];
    #pragma unroll
    for (int c = 0; c < NC; ++c) {
        const float* w = Wr + c * NH + lane * 8;
        float s = 0.f;
        #pragma unroll
        for (int j = 0; j < 8; ++j) s = fmaf(mv[j], w[j], s);
        #pragma unroll
        for (int off = 16; off > 0; off >>= 1)
            s += __shfl_xor_sync(0xFFFFFFFFu, s, off);
        p[c] = s;
    }
    if (lane < NC) out[b * NC + lane] = p[lane] + br[lane];
}

// ================= launcher =================
extern "C" void kernel_launch(void* const* d_in, const int* in_sizes, int n_in,
                              void* d_out, int out_size) {
    const float* x        = (const float*)d_in[0];
    const float* W_hidden = (const float*)d_in[1];
    const float* b_hidden = (const float*)d_in[2];
    const float* W_read   = (const float*)d_in[3];
    const float* b_read   = (const float*)d_in[4];
    float* out = (float*)d_out;

    cudaFuncSetAttribute(k_fused, cudaFuncAttributeMaxDynamicSharedMemorySize, SMEM_TOTAL);

    k_split<<<(NH * NF + 255) / 256, 256>>>(W_hidden);
    k_spike<<<(BF / 4) / 256, 256>>>(x);
    k_fused<<<dim3(NH / 64, NB / 64), 128, SMEM_TOTAL>>>(b_hidden);
    k_readout<<<NB / 8, 256>>>(W_read, b_read, out);
}

// round 6
// speedup vs baseline: 1.2370x; 1.2370x over previous
#include <cuda_runtime.h>
#include <cuda_bf16.h>
#include <cstdint>

#define NB 16384
#define NF 256
#define NH 256
#define NC 10
#define NT 100
#define BF (NB * NF)

#define DT_TAU_MEM 0.1f
#define SYN_DECAY  0.8f

// ---- device scratch (static, no allocation) ----
__device__ unsigned short g_Z[(size_t)NT * BF];     // layer-1 spikes, bf16 {0,1}
__device__ unsigned short g_Ws[2][NH * NF];         // W_hidden 2-way bf16 split
__device__ float          g_ms[(size_t)NB * NH];    // mean spike counts

// ================= kernel 0: split W into 2 bf16 planes =================
__global__ void k_split(const float* __restrict__ W) {
    int i = blockIdx.x * blockDim.x + threadIdx.x;
    if (i >= NH * NF) return;
    float w = W[i];
    __nv_bfloat16 hi = __float2bfloat16(w);
    float r1 = w - __bfloat162float(hi);
    __nv_bfloat16 mid = __float2bfloat16(r1);
    g_Ws[0][i] = *(unsigned short*)&hi;
    g_Ws[1][i] = *(unsigned short*)&mid;
}

// ================= kernel 1: layer-1 LIF spike trains =================
__global__ void k_spike(const float* __restrict__ X) {
    int gid = (blockIdx.x * blockDim.x + threadIdx.x) * 4;
    float x0 = X[gid], x1 = X[gid + 1], x2 = X[gid + 2], x3 = X[gid + 3];
    float v0 = 0.f, v1 = 0.f, v2 = 0.f, v3 = 0.f;
    float c0 = 0.f, c1 = 0.f, c2 = 0.f, c3 = 0.f;
    const unsigned short ONE = 0x3F80u, ZER = 0u;
    for (int t = 0; t < NT; ++t) {
        float d0 = fmaf(DT_TAU_MEM, c0 - v0, v0);
        float d1 = fmaf(DT_TAU_MEM, c1 - v1, v1);
        float d2 = fmaf(DT_TAU_MEM, c2 - v2, v2);
        float d3 = fmaf(DT_TAU_MEM, c3 - v3, v3);
        bool z0 = d0 > 1.0f, z1 = d1 > 1.0f, z2 = d2 > 1.0f, z3 = d3 > 1.0f;
        ushort4 pk = make_ushort4(z0 ? ONE : ZER, z1 ? ONE : ZER,
                                  z2 ? ONE : ZER, z3 ? ONE : ZER);
        reinterpret_cast<ushort4*>(g_Z + (size_t)t * BF)[gid >> 2] = pk;
        v0 = z0 ? 0.f : d0; v1 = z1 ? 0.f : d1;
        v2 = z2 ? 0.f : d2; v3 = z3 ? 0.f : d3;
        c0 = __fadd_rn(__fmul_rn(c0, SYN_DECAY), x0);
        c1 = __fadd_rn(__fmul_rn(c1, SYN_DECAY), x1);
        c2 = __fadd_rn(__fmul_rn(c2, SYN_DECAY), x2);
        c3 = __fadd_rn(__fmul_rn(c3, SYN_DECAY), x3);
    }
}

// ================= kernel 2: fused GEMM + layer-2 LIF scan =================
// CTA: 128 b-rows x 64 h-cols, 256 thr (4x2 warps of 32x32 warp tiles).
// W (2 splits, 64 rows) SMEM-resident; 128-row Z tile double-buffered via cp.async.

#define SROW_B 528                          // padded row bytes (264 bf16)
#define ROWSTEP16 8448                      // 16 * SROW_B
#define SW_BYTES (2 * 64 * SROW_B)          // 67584
#define SA_BYTES (128 * SROW_B)             // 67584
#define SWSPLIT  (64 * SROW_B)              // 33792
#define SMEM_TOTAL (SW_BYTES + 2 * SA_BYTES)  // 202752

#define LDSM4(R, ADDR) asm volatile( \
    "ldmatrix.sync.aligned.m8n8.x4.shared.b16 {%0,%1,%2,%3}, [%4];" \
    : "=r"((R)[0]), "=r"((R)[1]), "=r"((R)[2]), "=r"((R)[3]) : "r"(ADDR))

#define MMA(D, A, B0, B1) asm volatile( \
    "mma.sync.aligned.m16n8k16.row.col.f32.bf16.bf16.f32 " \
    "{%0,%1,%2,%3},{%4,%5,%6,%7},{%8,%9},{%0,%1,%2,%3};" \
    : "+f"((D)[0]), "+f"((D)[1]), "+f"((D)[2]), "+f"((D)[3]) \
    : "r"((A)[0]), "r"((A)[1]), "r"((A)[2]), "r"((A)[3]), "r"(B0), "r"(B1))

__device__ __forceinline__ void cp16(uint32_t dst, const void* src) {
    asm volatile("cp.async.cg.shared.global [%0], [%1], 16;" :: "r"(dst), "l"(src));
}
__device__ __forceinline__ void cp_commit() { asm volatile("cp.async.commit_group;"); }
__device__ __forceinline__ void cp_wait0()  { asm volatile("cp.async.wait_group 0;"); }

__global__ void __launch_bounds__(256, 1)
k_fused(const float* __restrict__ bhid) {
    extern __shared__ char smem[];
    const uint32_t su = (uint32_t)__cvta_generic_to_shared(smem);
    const uint32_t wbase  = su;
    const uint32_t zbase0 = su + SW_BYTES;
    const uint32_t zbase1 = su + SW_BYTES + SA_BYTES;

    const int tid = threadIdx.x;
    const int warp = tid >> 5, lane = tid & 31;
    const int warp_m = warp >> 1, warp_n = warp & 1;   // 4 x 2 warp grid
    const int hTile = blockIdx.x, bTile = blockIdx.y;

    // ---- prologue: W (2 splits x 64 rows) + Z(t=0) (128 rows) ----
    {
        // W: 2*64*32 = 4096 chunks of 16B
        for (int i = 0; i < 16; ++i) {
            int idx = tid + i * 256;
            int s = idx >> 11, rem = idx & 2047;
            int row = rem >> 5, ch = rem & 31;
            const char* src = (const char*)g_Ws[s] + ((size_t)(hTile * 64 + row) * 512) + ch * 16;
            cp16(wbase + s * SWSPLIT + row * SROW_B + ch * 16, src);
        }
        // Z(0): 128 rows * 32 chunks = 4096
        const char* zsrc = (const char*)g_Z + (size_t)(bTile * 128) * 512;
        for (int i = 0; i < 16; ++i) {
            int idx = tid + i * 256;
            int row = idx >> 5, ch = idx & 31;
            cp16(zbase0 + row * SROW_B + ch * 16, zsrc + (size_t)row * 512 + ch * 16);
        }
        cp_commit();
        cp_wait0();
        __syncthreads();
    }

    const int c2 = (lane & 3) * 2;
    const int r4 = lane >> 2;
    float bhv[8];
    #pragma unroll
    for (int nt = 0; nt < 4; ++nt)
        #pragma unroll
        for (int e1 = 0; e1 < 2; ++e1)
            bhv[nt * 2 + e1] = bhid[hTile * 64 + warp_n * 32 + nt * 8 + c2 + e1];

    const uint32_t aOff = (uint32_t)((warp_m * 32 + (lane & 15)) * SROW_B + (lane >> 4) * 16);
    const uint32_t bOff = (uint32_t)((warp_n * 32 + (lane & 15)) * SROW_B + (lane >> 4) * 16);

    float v2[32], i2[32], cnt[32];
    #pragma unroll
    for (int i = 0; i < 32; ++i) { v2[i] = 0.f; i2[i] = 0.f; cnt[i] = 0.f; }

    for (int t = 0; t < NT; ++t) {
        if (t < NT - 1) {
            uint32_t dst = ((t + 1) & 1) ? zbase1 : zbase0;
            const char* zsrc = (const char*)g_Z + (size_t)(t + 1) * BF * 2
                             + (size_t)(bTile * 128) * 512;
            for (int i = 0; i < 16; ++i) {
                int idx = tid + i * 256;
                int row = idx >> 5, ch = idx & 31;
                cp16(dst + row * SROW_B + ch * 16, zsrc + (size_t)row * 512 + ch * 16);
            }
            cp_commit();
        }

        const uint32_t zb = (t & 1) ? zbase1 : zbase0;
        float acc[2][4][4];
        #pragma unroll
        for (int mt = 0; mt < 2; ++mt)
            #pragma unroll
            for (int nt = 0; nt < 4; ++nt)
                #pragma unroll
                for (int e = 0; e < 4; ++e) acc[mt][nt][e] = 0.f;

        #pragma unroll 4
        for (int kc = 0; kc < 16; ++kc) {
            uint32_t a[2][4];
            LDSM4(a[0], zb + aOff + kc * 32);
            LDSM4(a[1], zb + aOff + ROWSTEP16 + kc * 32);
            #pragma unroll
            for (int s = 0; s < 2; ++s) {
                uint32_t b0[4], b1[4];
                LDSM4(b0, wbase + s * SWSPLIT + bOff + kc * 32);
                LDSM4(b1, wbase + s * SWSPLIT + bOff + ROWSTEP16 + kc * 32);
                #pragma unroll
                for (int mt = 0; mt < 2; ++mt) {
                    MMA(acc[mt][0], a[mt], b0[0], b0[2]);
                    MMA(acc[mt][1], a[mt], b0[1], b0[3]);
                    MMA(acc[mt][2], a[mt], b1[0], b1[2]);
                    MMA(acc[mt][3], a[mt], b1[1], b1[3]);
                }
            }
        }

        // fused layer-2 LIF update
        #pragma unroll
        for (int mt = 0; mt < 2; ++mt)
            #pragma unroll
            for (int nt = 0; nt < 4; ++nt)
                #pragma unroll
                for (int e = 0; e < 4; ++e) {
                    int s = (mt * 4 + nt) * 4 + e;
                    float h = acc[mt][nt][e] + bhv[nt * 2 + (e & 1)];
                    float vd = fmaf(DT_TAU_MEM, i2[s] - v2[s], v2[s]);
                    bool z = vd > 1.0f;
                    cnt[s] += z ? 1.0f : 0.0f;
                    v2[s] = z ? 0.0f : vd;
                    i2[s] = __fadd_rn(__fmul_rn(i2[s], SYN_DECAY), h);
                }

        if (t < NT - 1) { cp_wait0(); __syncthreads(); }
    }

    // write mean spikes
    #pragma unroll
    for (int mt = 0; mt < 2; ++mt)
        #pragma unroll
        for (int nt = 0; nt < 4; ++nt)
            #pragma unroll
            for (int e = 0; e < 4; ++e) {
                int s = (mt * 4 + nt) * 4 + e;
                int gb = bTile * 128 + warp_m * 32 + mt * 16 + r4 + (e >> 1) * 8;
                int gh = hTile * 64 + warp_n * 32 + nt * 8 + c2 + (e & 1);
                g_ms[(size_t)gb * NH + gh] = cnt[s] / 100.0f;
            }
}

// ================= kernel 3: readout (8 rows per warp, Wr in regs) =================
__global__ void k_readout(const float* __restrict__ Wr,
                          const float* __restrict__ br,
                          float* __restrict__ out) {
    int warp = threadIdx.x >> 5, lane = threadIdx.x & 31;
    // cache this lane's 8-column slice of all 10 readout rows
    float w[NC][8];
    #pragma unroll
    for (int c = 0; c < NC; ++c) {
        const float4* wp = reinterpret_cast<const float4*>(Wr + c * NH + lane * 8);
        float4 w0 = wp[0], w1 = wp[1];
        w[c][0] = w0.x; w[c][1] = w0.y; w[c][2] = w0.z; w[c][3] = w0.w;
        w[c][4] = w1.x; w[c][5] = w1.y; w[c][6] = w1.z; w[c][7] = w1.w;
    }
    float brv = (lane < NC) ? br[lane] : 0.f;

    int b0 = blockIdx.x * 64 + warp * 8;
    for (int r = 0; r < 8; ++r) {
        int b = b0 + r;
        const float4* msp = reinterpret_cast<const float4*>(g_ms + (size_t)b * NH);
        float4 m0 = msp[lane * 2], m1 = msp[lane * 2 + 1];
        float mv[8] = {m0.x, m0.y, m0.z, m0.w, m1.x, m1.y, m1.z, m1.w};
        float p[NC];
        #pragma unroll
        for (int c = 0; c < NC; ++c) {
            float s = 0.f;
            #pragma unroll
            for (int j = 0; j < 8; ++j) s = fmaf(mv[j], w[c][j], s);
            p[c] = s;
        }
        #pragma unroll
        for (int off = 16; off > 0; off >>= 1)
            #pragma unroll
            for (int c = 0; c < NC; ++c)
                p[c] += __shfl_xor_sync(0xFFFFFFFFu, p[c], off);
        if (lane < NC) out[b * NC + lane] = p[lane] + brv;
    }
}

// ================= launcher =================
extern "C" void kernel_launch(void* const* d_in, const int* in_sizes, int n_in,
                              void* d_out, int out_size) {
    const float* x        = (const float*)d_in[0];
    const float* W_hidden = (const float*)d_in[1];
    const float* b_hidden = (const float*)d_in[2];
    const float* W_read   = (const float*)d_in[3];
    const float* b_read   = (const float*)d_in[4];
    float* out = (float*)d_out;

    cudaFuncSetAttribute(k_fused, cudaFuncAttributeMaxDynamicSharedMemorySize, SMEM_TOTAL);

    k_split<<<(NH * NF + 255) / 256, 256>>>(W_hidden);
    k_spike<<<(BF / 4) / 256, 256>>>(x);
    k_fused<<<dim3(NH / 64, NB / 128), 256, SMEM_TOTAL>>>(b_hidden);
    k_readout<<<NB / 64, 256>>>(W_read, b_read, out);
}